// round 5
// baseline (speedup 1.0000x reference)
#include <cuda_runtime.h>

// ---------------- problem constants ----------------
#define NN    16384     // nodes (B*NPER)
#define EE    65536     // edges
#define HH    32        // hidden
#define BBAT  32        // batch
#define NPERB 512
#define NLAY  4
#define KTOT  320       // 256 (c (x) x) + 32 (bias path) + 32 (root path)
#define NPB   32        // nodes per layer-block
#define APITCH 324      // A pitch: %32==4 -> conflict-free, rows 16B-aligned for LDS.128
#define RPITCH 36       // reduction staging pitch
// dynamic smem float offsets
#define OFF_AS 0
#define OFF_BS 10368    // 32*324
#define OFF_CS 20608    // +320*32
#define SMEMF  20736
#define SMEMB  (SMEMF * 4)

// ---------------- scratch (static device globals; zero at load) ----------------
__device__ __align__(16) float g_xbuf[2][NN * HH];     // ping-pong node features
__device__ __align__(16) float g_B[NLAY * KTOT * HH];  // fused per-layer weights (160KB)
__device__ int   g_deg[NN];                            // zeroed by k_final for next replay
__device__ float g_invdeg[NN];
__device__ int   g_rowstart[NN + 1];
__device__ int   g_cursor[NN];
__device__ int   g_payload[EE];                        // (src<<4)|attr, grouped by dst
__device__ int   g_bsum[64];
__device__ int   g_barrier;                            // grid barrier (reset each run)
__device__ int   g_done;

// ---------------- f32x2 helpers ----------------
__device__ __forceinline__ unsigned long long fma2(unsigned long long a,
                                                   unsigned long long b,
                                                   unsigned long long c) {
    unsigned long long d;
    asm("fma.rn.f32x2 %0, %1, %2, %3;" : "=l"(d) : "l"(a), "l"(b), "l"(c));
    return d;
}
__device__ __forceinline__ unsigned long long rep2(float a) {
    unsigned int u = __float_as_uint(a);
    unsigned long long d;
    asm("mov.b64 %0, {%1, %1};" : "=l"(d) : "r"(u));
    return d;
}

// ================= K1: fused setup (init x, build B, count degrees) ==========
__global__ __launch_bounds__(256) void k_setup(const int* __restrict__ xn,
                                               const float* __restrict__ nemb,
                                               const float* __restrict__ lin_w,
                                               const float* __restrict__ lin_b,
                                               const float* __restrict__ root_w,
                                               const int* __restrict__ edge_index) {
    int b = blockIdx.x, t = threadIdx.x;
    if (b < 512) {
        int i = b * 256 + t;                 // < NN*HH/4
        int node = i >> 3, q = i & 7;
        float4 v = __ldg((const float4*)(nemb + xn[node] * HH + q * 4));
        ((float4*)g_xbuf[0])[i] = v;
    } else if (b < 672) {
        int i = (b - 512) * 256 + t;         // < NLAY*KTOT*HH
        int l = i / (KTOT * HH);
        int rem = i - l * KTOT * HH;
        int r = rem >> 5, o = rem & 31;
        float v;
        if (r < 256)      v = lin_w[l * 8192 + (r >> 5) * 1024 + (r & 31) * 32 + o];
        else if (r < 288) v = lin_b[l * 1024 + (r - 256) * 32 + o];
        else              v = root_w[l * 1024 + (r - 288) * 32 + o];
        g_B[i] = v;
    } else {
        int i = (b - 672) * 256 + t;         // < EE/4
        int4 d4 = __ldg((const int4*)(edge_index + EE) + i);
        atomicAdd(&g_deg[d4.x], 1);
        atomicAdd(&g_deg[d4.y], 1);
        atomicAdd(&g_deg[d4.z], 1);
        atomicAdd(&g_deg[d4.w], 1);
    }
}

// ================= K2: fused scan + scatter (64 blocks, grid barriers) ========
// All 64 blocks are resident (tiny footprint), so spin barriers cannot deadlock.
// Counters end at 0 every run -> deterministic under graph replay.
__global__ __launch_bounds__(256) void k_scan_scatter(const int* __restrict__ edge_index,
                                                      const int* __restrict__ edge_attr) {
    __shared__ int sw[8];
    __shared__ int sb[64];
    int tid = threadIdx.x, w = tid >> 5, lane = tid & 31, b = blockIdx.x;
    int n = b * 256 + tid;
    int d = g_deg[n];

    // warp inclusive scan
    int incl = d;
#pragma unroll
    for (int off = 1; off < 32; off <<= 1) {
        int v = __shfl_up_sync(0xFFFFFFFFu, incl, off);
        if (lane >= off) incl += v;
    }
    if (lane == 31) sw[w] = incl;
    __syncthreads();
    int woff = 0, btot = 0;
#pragma unroll
    for (int j = 0; j < 8; j++) { if (j < w) woff += sw[j]; btot += sw[j]; }

    // publish block total; grid barrier #1
    if (tid == 0) {
        g_bsum[b] = btot;
        __threadfence();
        atomicAdd(&g_barrier, 1);
        while (atomicAdd(&g_barrier, 0) < 64) { }
        __threadfence();
    }
    __syncthreads();

    if (tid < 64) sb[tid] = g_bsum[tid];
    __syncthreads();
    int base = 0;
    for (int j = 0; j < b; j++) base += sb[j];

    int excl = base + woff + incl - d;
    g_rowstart[n] = excl;
    g_cursor[n]   = excl;
    g_invdeg[n]   = 1.0f / (float)(d > 0 ? d : 1);
    if (n == NN - 1) g_rowstart[NN] = excl + d;

    // grid barrier #2 (cursors globally visible)
    __threadfence();
    __syncthreads();
    if (tid == 0) {
        atomicAdd(&g_barrier, 1);
        while (atomicAdd(&g_barrier, 0) < 128) { }
        __threadfence();
    }
    __syncthreads();

    // scatter this block's 1024 edges
#pragma unroll
    for (int q = 0; q < 4; q++) {
        int e = b * 1024 + q * 256 + tid;
        int dd = edge_index[EE + e];
        int pos = atomicAdd(&g_cursor[dd], 1);
        g_payload[pos] = (edge_index[e] << 4) | edge_attr[e];
    }
    __syncthreads();
    if (tid == 0) {
        int c = atomicAdd(&g_done, 1);
        if (c == 63) { g_done = 0; g_barrier = 0; __threadfence(); }
    }
}

// ================= fused layer =================================================
// Phase 1 (edge agg): 8 warps x 4 interleaved nodes, lane = feature, payload
//   prefetched 1 iteration ahead. Writes A (32 x 320, pitch 324) into smem.
// Phase 2 (GEMM): lane = row, warp w takes k-slice [w*40, w*40+40). Per 4k:
//   1 LDS.128 (A, conflict-free) + 4x(8 broadcast LDS.128 B + 16 FFMA2).
__global__ __launch_bounds__(256, 2) void k_layer(const float* __restrict__ eemb,
                                                  const float* __restrict__ conv_b,
                                                  int inbuf, int l, int do_relu) {
    extern __shared__ float smem[];
    float* As = smem + OFF_AS;
    float* Bs = smem + OFF_BS;
    float* cs = smem + OFF_CS;
    int tid = threadIdx.x;

    // stage B_l (40KB) into smem; issued first so latency hides under edge phase
    const float4* gBl = (const float4*)(g_B + l * (KTOT * HH));
#pragma unroll
    for (int i = 0; i < 10; i++)
        ((float4*)Bs)[tid + i * 256] = __ldg(gBl + tid + i * 256);
    if (tid < 128) cs[tid] = fmaxf(eemb[l * 128 + tid], 0.0f);

    const float* __restrict__ xin = g_xbuf[inbuf];
    int w = tid >> 5, lane = tid & 31;
    int nl0 = w * 4;
    int ng0 = blockIdx.x * NPB + nl0;

    int rs = 0;
    if (lane < 5) rs = g_rowstart[ng0 + lane];
    int r0 = __shfl_sync(0xFFFFFFFFu, rs, 0);
    int r1 = __shfl_sync(0xFFFFFFFFu, rs, 1);
    int r2 = __shfl_sync(0xFFFFFFFFu, rs, 2);
    int r3 = __shfl_sync(0xFFFFFFFFu, rs, 3);
    int r4 = __shfl_sync(0xFFFFFFFFu, rs, 4);
    int beg[4] = {r0, r1, r2, r3};
    int cnt[4] = {r1 - r0, r2 - r1, r3 - r2, r4 - r3};
    int maxc = max(max(cnt[0], cnt[1]), max(cnt[2], cnt[3]));

    float acc[4][9];
#pragma unroll
    for (int i = 0; i < 4; i++)
#pragma unroll
        for (int j = 0; j < 9; j++) acc[i][j] = 0.0f;

    __syncthreads();   // cs ready

    // payload prefetch pipeline (depth 1)
    int pcur[4];
#pragma unroll
    for (int i = 0; i < 4; i++) pcur[i] = (0 < cnt[i]) ? g_payload[beg[i]] : -1;

    for (int t = 0; t < maxc; t++) {
        int pnext[4];
#pragma unroll
        for (int i = 0; i < 4; i++)
            pnext[i] = (t + 1 < cnt[i]) ? g_payload[beg[i] + t + 1] : -1;
        float xv[4];
#pragma unroll
        for (int i = 0; i < 4; i++)
            xv[i] = (pcur[i] >= 0) ? __ldg(&xin[(pcur[i] >> 4) * HH + lane]) : 0.0f;
#pragma unroll
        for (int i = 0; i < 4; i++) {
            const float* cc = &cs[(pcur[i] & 15) * 8];
#pragma unroll
            for (int j = 0; j < 8; j++) acc[i][j] = fmaf(cc[j], xv[i], acc[i][j]);
            acc[i][8] += xv[i];
        }
#pragma unroll
        for (int i = 0; i < 4; i++) pcur[i] = pnext[i];
    }

#pragma unroll
    for (int i = 0; i < 4; i++) {
        float inv = g_invdeg[ng0 + i];
        float* Arow = As + (nl0 + i) * APITCH;
#pragma unroll
        for (int j = 0; j < 9; j++) Arow[j * 32 + lane] = acc[i][j] * inv;
        Arow[288 + lane] = xin[(ng0 + i) * HH + lane];   // root path, unscaled
    }
    __syncthreads();

    // ---------------- GEMM phase: lane = row, warp = k-slice ----------------
    {
        const float* __restrict__ Ar = As + lane * APITCH;
        unsigned long long ac[16];
#pragma unroll
        for (int c = 0; c < 16; c++) ac[c] = 0ull;

        int k0 = w * 40;
#pragma unroll 1
        for (int k = k0; k < k0 + 40; k += 4) {
            float4 a4 = *(const float4*)(Ar + k);
#pragma unroll
            for (int kk = 0; kk < 4; kk++) {
                float a = (kk == 0) ? a4.x : (kk == 1) ? a4.y : (kk == 2) ? a4.z : a4.w;
                unsigned long long ar = rep2(a);
                const ulonglong2* Br = (const ulonglong2*)(Bs + ((k + kk) << 5));
#pragma unroll
                for (int q = 0; q < 8; q++) {
                    ulonglong2 bb = Br[q];
                    ac[2 * q]     = fma2(ar, bb.x, ac[2 * q]);
                    ac[2 * q + 1] = fma2(ar, bb.y, ac[2 * q + 1]);
                }
            }
        }
        __syncthreads();   // all done READING As; safe to overwrite
        float* Rp = As + w * 1152 + lane * RPITCH;
#pragma unroll
        for (int c = 0; c < 16; c++)
            *(unsigned long long*)(Rp + 2 * c) = ac[c];
    }
    __syncthreads();

    // ---------------- reduce 8 partials + epilogue ----------------
    {
        int row = tid >> 3, c4 = (tid & 7) * 4;
        float4 s = make_float4(0.f, 0.f, 0.f, 0.f);
#pragma unroll
        for (int w2 = 0; w2 < 8; w2++) {
            float4 v = *(const float4*)(As + w2 * 1152 + row * RPITCH + c4);
            s.x += v.x; s.y += v.y; s.z += v.z; s.w += v.w;
        }
        s.x += conv_b[l * HH + c4 + 0];
        s.y += conv_b[l * HH + c4 + 1];
        s.z += conv_b[l * HH + c4 + 2];
        s.w += conv_b[l * HH + c4 + 3];
        if (do_relu) {
            s.x = fmaxf(s.x, 0.f); s.y = fmaxf(s.y, 0.f);
            s.z = fmaxf(s.z, 0.f); s.w = fmaxf(s.w, 0.f);
        }
        float* __restrict__ xout = g_xbuf[inbuf ^ 1];
        *(float4*)&xout[(blockIdx.x * NPB + row) * HH + c4] = s;
    }
}

// ================= readout (+ zero g_deg for next replay) ====================
__global__ __launch_bounds__(256) void k_final(const int* __restrict__ metal_idx,
                                               const int* __restrict__ loop_edge,
                                               const int* __restrict__ loop_pair,
                                               const float* __restrict__ f_w,
                                               const float* __restrict__ f_b,
                                               float* __restrict__ out) {
    int gid = blockIdx.x * 256 + threadIdx.x;
    if (gid < NN) g_deg[gid] = 0;

    int gw = blockIdx.x * 8 + (threadIdx.x >> 5);
    int lane = threadIdx.x & 31;
    int b = gw >> 7, p = gw & 127;
    const float* __restrict__ x = g_xbuf[0];   // NLAY even -> final in buf 0

    int mnode = b * NPERB + metal_idx[b];
    float xm = x[mnode * HH + lane];

    int s, t;
    if (p < 64) {
        s = loop_edge[(b * 64 + p) * 2 + 0];
        t = loop_edge[(b * 64 + p) * 2 + 1];
    } else {
        int q = p - 64;
        s = loop_pair[(b * 64 + q) * 2 + 0];
        t = loop_pair[(b * 64 + q) * 2 + 1];
    }
    float xs = x[(b * NPERB + s) * HH + lane];
    float xt = x[(b * NPERB + t) * HH + lane];
    float v  = xm * (xs + xt) - xs * xt;
    float fh = xm * f_w[lane];
#pragma unroll
    for (int off = 16; off; off >>= 1) {
        v  += __shfl_xor_sync(0xFFFFFFFFu, v, off);
        fh += __shfl_xor_sync(0xFFFFFFFFu, fh, off);
    }
    if (lane == 0)
        out[b * 128 + p] = (p < 64) ? (v - (fh + f_b[0])) : -v;
}

// ================= launch ====================================================
extern "C" void kernel_launch(void* const* d_in, const int* in_sizes, int n_in,
                              void* d_out, int out_size) {
    const int*   x_nodes    = (const int*)d_in[0];
    const int*   edge_index = (const int*)d_in[1];
    const int*   edge_attr  = (const int*)d_in[2];
    const int*   metal_idx  = (const int*)d_in[3];
    const int*   loop_edge  = (const int*)d_in[4];
    const int*   loop_pair  = (const int*)d_in[5];
    const float* node_emb   = (const float*)d_in[6];
    const float* edge_emb   = (const float*)d_in[7];
    const float* lin_w      = (const float*)d_in[8];
    const float* lin_b      = (const float*)d_in[9];
    const float* root_w     = (const float*)d_in[10];
    const float* conv_b     = (const float*)d_in[11];
    const float* f_w        = (const float*)d_in[12];
    const float* f_b        = (const float*)d_in[13];
    float* out = (float*)d_out;

    cudaFuncSetAttribute(k_layer, cudaFuncAttributeMaxDynamicSharedMemorySize, SMEMB);

    k_setup       <<<736, 256>>>(x_nodes, node_emb, lin_w, lin_b, root_w, edge_index);
    k_scan_scatter<<<64, 256>>>(edge_index, edge_attr);

    for (int l = 0; l < NLAY; l++) {
        int inb = l & 1;
        k_layer<<<NN / NPB, 256, SMEMB>>>(edge_emb, conv_b, inb, l, (l < NLAY - 1) ? 1 : 0);
    }

    k_final<<<512, 256>>>(metal_idx, loop_edge, loop_pair, f_w, f_b, out);
}